// round 14
// baseline (speedup 1.0000x reference)
#include <cuda_runtime.h>
#include <cuda_bf16.h>
#include <cuda_fp16.h>
#include <cstdint>

static constexpr int NN = 100000;   // nodes
static constexpr int D  = 64;       // feature dim
static constexpr int NE = 1000000;  // edges

static constexpr int SCAN_T = 512;
static constexpr int NSCB   = (NN + SCAN_T - 1) / SCAN_T;   // 196

// Scratch (device globals — no allocation allowed)
__device__ uint4          g_hA[NN * 8];   // h fp16 ping (64 halves = 8 uint4/row)
__device__ uint4          g_hB[NN * 8];   // h fp16 pong
__device__ unsigned short g_wh[3 * 4096]; // W planes hi, [n*64+k], layers {1,2,out}
__device__ unsigned short g_wl[3 * 4096]; // W planes lo
__device__ float g_dinv[NN];
__device__ int   g_degi[NN];      // zero at entry (BSS first call; csr_fill re-zeros)
__device__ int   g_off [NN + 1];
__device__ int   g_cur [NN];
__device__ int   g_scan[NN];
__device__ int   g_bsum[NSCB];
__device__ int   g_csr [NE];      // src ids grouped by dst

// ---------------------------------------------------------------------------
// Per-block int64-vs-int32 detection (JAX may silently downcast edge_index).
__device__ __forceinline__ int block_detect64(const int* __restrict__ w) {
    __shared__ int s_flag;
    if (threadIdx.x == 0) s_flag = 0;
    __syncthreads();
    if (threadIdx.x < 64 && w[2 * threadIdx.x + 1]) atomicOr(&s_flag, 1);
    __syncthreads();
    return s_flag == 0;
}

__device__ __forceinline__ int edge_at(const void* ei, int is64, long long pos) {
    if (is64) return (int)((const long long*)ei)[pos];
    return ((const int*)ei)[pos];
}

__global__ void degi_count(const void* __restrict__ ei) {
    int is64 = block_detect64((const int*)ei);
    int e = blockIdx.x * 256 + threadIdx.x;
    if (e < NE) atomicAdd(&g_degi[edge_at(ei, is64, (long long)NE + e)], 1);
}

// ---- prefix scans (warp-shuffle based) ------------------------------------
__global__ void scan1() {
    int i = blockIdx.x * SCAN_T + threadIdx.x;
    int lane = threadIdx.x & 31, w = threadIdx.x >> 5;
    int s = (i < NN) ? g_degi[i] : 0;
    #pragma unroll
    for (int off = 1; off < 32; off <<= 1) {
        int t = __shfl_up_sync(0xFFFFFFFFu, s, off);
        if (lane >= off) s += t;
    }
    __shared__ int wsum[16];
    if (lane == 31) wsum[w] = s;
    __syncthreads();
    if (w == 0) {
        int t = (lane < 16) ? wsum[lane] : 0;
        #pragma unroll
        for (int off = 1; off < 16; off <<= 1) {
            int u = __shfl_up_sync(0xFFFFFFFFu, t, off);
            if (lane >= off) t += u;
        }
        if (lane < 16) wsum[lane] = t;
    }
    __syncthreads();
    int incl = s + (w > 0 ? wsum[w - 1] : 0);
    if (i < NN) g_scan[i] = incl;
    if (threadIdx.x == SCAN_T - 1) g_bsum[blockIdx.x] = incl;
}

// Fused: shuffle-scan of the 196 block sums + offsets + cursor + dinv.
__global__ void scan23() {
    __shared__ int bsx[256];
    {
        int lane = threadIdx.x & 31, w = threadIdx.x >> 5;
        int s = (threadIdx.x < NSCB) ? g_bsum[threadIdx.x] : 0;
        #pragma unroll
        for (int off = 1; off < 32; off <<= 1) {
            int t = __shfl_up_sync(0xFFFFFFFFu, s, off);
            if (lane >= off) s += t;
        }
        __shared__ int wsum[8];
        if (lane == 31) wsum[w] = s;
        __syncthreads();
        if (w == 0 && lane < 8) {
            int t = wsum[lane];
            #pragma unroll
            for (int off = 1; off < 8; off <<= 1) {
                int u = __shfl_up_sync(0xFFu, t, off);
                if (lane >= off) t += u;
            }
            wsum[lane] = t;
        }
        __syncthreads();
        bsx[threadIdx.x] = s + (w > 0 ? wsum[w - 1] : 0);
    }
    __syncthreads();
    int i = blockIdx.x * 256 + threadIdx.x;
    if (i >= NN) return;
    int b  = i / SCAN_T;
    int di = g_degi[i];
    int incl = g_scan[i] + (b > 0 ? bsx[b - 1] : 0);
    g_off[i + 1] = incl;
    if (i == 0) g_off[0] = 0;
    g_cur[i] = incl - di;
    g_dinv[i] = rsqrtf(1.0f + (float)di);
}

// Fill CSR; also re-zero g_degi so the NEXT invocation starts clean.
__global__ void csr_fill(const void* __restrict__ ei) {
    int is64 = block_detect64((const int*)ei);
    int e = blockIdx.x * 256 + threadIdx.x;
    if (e < NN) g_degi[e] = 0;
    if (e >= NE) return;
    int src = edge_at(ei, is64, e);
    int dst = edge_at(ei, is64, (long long)NE + e);
    int pos = atomicAdd(&g_cur[dst], 1);
    g_csr[pos] = src;
}

// ---------------------------------------------------------------------------
__device__ __forceinline__ void split_bf16(float x, unsigned short& h, unsigned short& l) {
    __nv_bfloat16 hb = __float2bfloat16(x);
    __nv_bfloat16 lb = __float2bfloat16(x - __bfloat162float(hb));
    h = __bfloat16_as_ushort(hb);
    l = __bfloat16_as_ushort(lb);
}

// Pre-split W planes for layers {1,2,out}: [n*64+k] hi/lo from row-major W[k][n].
__global__ void wconv(const float* __restrict__ Ws, const float* __restrict__ Wout) {
    int idx = blockIdx.x * 256 + threadIdx.x;     // 0 .. 3*4096
    if (idx >= 3 * 4096) return;
    int l   = idx >> 12;
    int rem = idx & 4095;
    int k = rem >> 6, n = rem & 63;
    float v = (l < 2) ? Ws[(l + 1) * 4096 + rem] : Wout[rem];
    unsigned short h, lo;
    split_bf16(v, h, lo);
    g_wh[l * 4096 + n * 64 + k] = h;
    g_wl[l * 4096 + n * 64 + k] = lo;
}

// ---------------------------------------------------------------------------
// Tensor-core machinery (mma.sync bf16, 3-pass compensation).
static constexpr int HSTR  = 72;   // halves per row (64 + 8 pad)

__device__ __forceinline__ uint32_t smem_u32(const void* p) {
    uint32_t a;
    asm("{ .reg .u64 t; cvta.to.shared.u64 t, %1; cvt.u32.u64 %0, t; }"
        : "=r"(a) : "l"(p));
    return a;
}
__device__ __forceinline__ void ldsm4(uint32_t& r0, uint32_t& r1, uint32_t& r2,
                                      uint32_t& r3, uint32_t addr) {
    asm volatile("ldmatrix.sync.aligned.m8n8.x4.shared.b16 {%0,%1,%2,%3}, [%4];"
                 : "=r"(r0), "=r"(r1), "=r"(r2), "=r"(r3) : "r"(addr));
}
__device__ __forceinline__ void mma16816(float* c, const uint32_t* a,
                                         uint32_t b0, uint32_t b1) {
    asm volatile(
        "mma.sync.aligned.m16n8k16.row.col.f32.bf16.bf16.f32 "
        "{%0,%1,%2,%3}, {%4,%5,%6,%7}, {%8,%9}, {%0,%1,%2,%3};"
        : "+f"(c[0]), "+f"(c[1]), "+f"(c[2]), "+f"(c[3])
        : "r"(a[0]), "r"(a[1]), "r"(a[2]), "r"(a[3]), "r"(b0), "r"(b1));
}

// ======================= Layer-1 GEMM (128-row tile) =======================
static constexpr int G_AH = 0;
static constexpr int G_AL = G_AH + 128 * HSTR * 2;   // 18432
static constexpr int G_BH = G_AL + 128 * HSTR * 2;   // 36864
static constexpr int G_BL = G_BH + 64 * HSTR * 2;    // 46080
static constexpr int G_TOT = G_BL + 64 * HSTR * 2;   // 55296

__global__ void __launch_bounds__(256) gemm_f32(
        const float* __restrict__ X, const float* __restrict__ W,
        __half* __restrict__ Yh) {
    extern __shared__ char smem[];
    const int tid  = threadIdx.x;
    const long long base = (long long)blockIdx.x * 128;

    #pragma unroll
    for (int i = 0; i < 8; i++) {
        int idx  = tid + i * 256;
        int row  = idx >> 4;
        int k    = (idx & 15) * 4;
        float4 v = make_float4(0.f, 0.f, 0.f, 0.f);
        if (base + row < NN)
            v = ((const float4*)X)[(base + row) * 16 + (k >> 2)];
        unsigned short h0, l0, h1, l1, h2v, l2v, h3, l3;
        split_bf16(v.x, h0, l0); split_bf16(v.y, h1, l1);
        split_bf16(v.z, h2v, l2v); split_bf16(v.w, h3, l3);
        unsigned long long hp = (unsigned long long)h0
            | ((unsigned long long)h1 << 16) | ((unsigned long long)h2v << 32)
            | ((unsigned long long)h3 << 48);
        unsigned long long lp = (unsigned long long)l0
            | ((unsigned long long)l1 << 16) | ((unsigned long long)l2v << 32)
            | ((unsigned long long)l3 << 48);
        uint32_t off = (uint32_t)(row * HSTR + k) * 2;
        *(unsigned long long*)(smem + G_AH + off) = hp;
        *(unsigned long long*)(smem + G_AL + off) = lp;
    }
    #pragma unroll
    for (int i = 0; i < 16; i++) {
        int idx = tid + i * 256;
        int k = idx >> 6, n = idx & 63;
        unsigned short h, l;
        split_bf16(W[idx], h, l);
        uint32_t off = (uint32_t)(n * HSTR + k) * 2;
        *(unsigned short*)(smem + G_BH + off) = h;
        *(unsigned short*)(smem + G_BL + off) = l;
    }
    __syncthreads();

    const int wid  = tid >> 5;
    const int lane = tid & 31;
    const uint32_t sb = smem_u32(smem);
    const int r0w = wid * 16;
    const int li  = lane >> 3;
    const int lw  = lane & 7;
    const uint32_t a_off =
        (uint32_t)(((r0w + (li & 1) * 8 + lw) * HSTR + (li >> 1) * 8) * 2);
    const uint32_t b_off =
        (uint32_t)((((li >> 1) * 8 + lw) * HSTR + (li & 1) * 8) * 2);

    float acc[8][4];
    #pragma unroll
    for (int nt = 0; nt < 8; nt++)
        #pragma unroll
        for (int q = 0; q < 4; q++) acc[nt][q] = 0.f;

    const uint32_t aB[3] = { sb + G_AH, sb + G_AH, sb + G_AL };
    const uint32_t bB[3] = { sb + G_BH, sb + G_BL, sb + G_BH };
    #pragma unroll
    for (int pass = 0; pass < 3; pass++) {
        #pragma unroll
        for (int kt = 0; kt < 4; kt++) {
            uint32_t a[4];
            ldsm4(a[0], a[1], a[2], a[3], aB[pass] + a_off + kt * 32);
            #pragma unroll
            for (int ntp = 0; ntp < 4; ntp++) {
                uint32_t b0, b1, b2, b3;
                ldsm4(b0, b1, b2, b3,
                      bB[pass] + b_off + (uint32_t)(ntp * 16 * HSTR * 2) + kt * 32);
                mma16816(acc[2 * ntp],     a, b0, b1);
                mma16816(acc[2 * ntp + 1], a, b2, b3);
            }
        }
    }

    const int rA = r0w + (lane >> 2);
    long long gA = base + rA, gB = gA + 8;
    bool vA = gA < NN, vB = gB < NN;
    #pragma unroll
    for (int nt = 0; nt < 8; nt++) {
        int cg = nt * 8 + (lane & 3) * 2;
        if (vA) *(__half2*)&Yh[gA * 64 + cg] = __floats2half2_rn(acc[nt][0], acc[nt][1]);
        if (vB) *(__half2*)&Yh[gB * 64 + cg] = __floats2half2_rn(acc[nt][2], acc[nt][3]);
    }
}

// ======================= Fused gather + GEMM (64-row tile) =================
static constexpr int F_AH = 0;
static constexpr int F_AL = F_AH + 64 * HSTR * 2;    // 9216
static constexpr int F_BH = F_AL + 64 * HSTR * 2;    // 18432
static constexpr int F_BL = F_BH + 64 * HSTR * 2;    // 27648
static constexpr int F_TOT = F_BL + 64 * HSTR * 2;   // 36864

// Accumulate one source node's 16 columns into a[16].
__device__ __forceinline__ void acc1(const uint4* __restrict__ Hin, int s, int sub,
                                     float* a) {
    float d = g_dinv[s];
    uint4 u0 = Hin[s * 8 + sub * 2];
    uint4 u1 = Hin[s * 8 + sub * 2 + 1];
    const __half2* q0 = (const __half2*)&u0;
    const __half2* q1 = (const __half2*)&u1;
    #pragma unroll
    for (int q = 0; q < 4; q++) {
        float2 f0 = __half22float2(q0[q]);
        float2 f1 = __half22float2(q1[q]);
        a[2 * q]         = fmaf(d, f0.x, a[2 * q]);
        a[2 * q + 1]     = fmaf(d, f0.y, a[2 * q + 1]);
        a[8 + 2 * q]     = fmaf(d, f1.x, a[8 + 2 * q]);
        a[8 + 2 * q + 1] = fmaf(d, f1.y, a[8 + 2 * q + 1]);
    }
}

// Gather layer activations for 64 nodes straight into smem bf16 planes
// (4 threads/node, 16 cols each; 4x-unrolled edge loop with int4 index loads),
// then multiply by pre-split W planes.
__global__ void __launch_bounds__(256) fused_gg(
        const uint4* __restrict__ Hin, const float* __restrict__ bias_g,
        const unsigned short* __restrict__ Wh, const unsigned short* __restrict__ Wl,
        __half* __restrict__ Hout, float* __restrict__ Fout,
        const float* __restrict__ bias_f) {
    extern __shared__ char smem[];
    const int tid  = threadIdx.x;
    const long long base = (long long)blockIdx.x * 64;

    // ---- phase 1: gather (4 threads per node, 16 cols each) ----
    {
        int node = (int)base + (tid >> 2);
        int sub  = tid & 3;
        unsigned short hs[16], ls[16];
        if (node < NN) {
            float dv = g_dinv[node];
            float a[16];
            {
                uint4 v0 = Hin[node * 8 + sub * 2];
                uint4 v1 = Hin[node * 8 + sub * 2 + 1];
                const __half2* p0 = (const __half2*)&v0;
                const __half2* p1 = (const __half2*)&v1;
                #pragma unroll
                for (int q = 0; q < 4; q++) {
                    float2 f0 = __half22float2(p0[q]);
                    float2 f1 = __half22float2(p1[q]);
                    a[2 * q]      = dv * f0.x;
                    a[2 * q + 1]  = dv * f0.y;
                    a[8 + 2 * q]     = dv * f1.x;
                    a[8 + 2 * q + 1] = dv * f1.y;
                }
            }
            int e   = g_off[node];
            int end = g_off[node + 1];
            // peel to int4 alignment of the index stream
            while ((e & 3) && e < end) { acc1(Hin, __ldg(&g_csr[e]), sub, a); e++; }
            // 4 edges per iteration: one LDG.128 index fetch, batched H loads
            for (; e + 3 < end; e += 4) {
                int4 s4 = *(const int4*)&g_csr[e];
                float d0 = g_dinv[s4.x], d1 = g_dinv[s4.y];
                float d2 = g_dinv[s4.z], d3 = g_dinv[s4.w];
                uint4 A0 = Hin[s4.x * 8 + sub * 2], B0 = Hin[s4.x * 8 + sub * 2 + 1];
                uint4 A1 = Hin[s4.y * 8 + sub * 2], B1 = Hin[s4.y * 8 + sub * 2 + 1];
                uint4 A2 = Hin[s4.z * 8 + sub * 2], B2 = Hin[s4.z * 8 + sub * 2 + 1];
                uint4 A3 = Hin[s4.w * 8 + sub * 2], B3 = Hin[s4.w * 8 + sub * 2 + 1];
                const __half2 *a0 = (const __half2*)&A0, *b0 = (const __half2*)&B0;
                const __half2 *a1 = (const __half2*)&A1, *b1 = (const __half2*)&B1;
                const __half2 *a2 = (const __half2*)&A2, *b2 = (const __half2*)&B2;
                const __half2 *a3 = (const __half2*)&A3, *b3 = (const __half2*)&B3;
                #pragma unroll
                for (int q = 0; q < 4; q++) {
                    float2 f0 = __half22float2(a0[q]);
                    float2 f1 = __half22float2(a1[q]);
                    float2 f2 = __half22float2(a2[q]);
                    float2 f3 = __half22float2(a3[q]);
                    a[2 * q]     = fmaf(d0, f0.x, fmaf(d1, f1.x,
                                    fmaf(d2, f2.x, fmaf(d3, f3.x, a[2 * q]))));
                    a[2 * q + 1] = fmaf(d0, f0.y, fmaf(d1, f1.y,
                                    fmaf(d2, f2.y, fmaf(d3, f3.y, a[2 * q + 1]))));
                    float2 g0 = __half22float2(b0[q]);
                    float2 g1 = __half22float2(b1[q]);
                    float2 g2 = __half22float2(b2[q]);
                    float2 g3 = __half22float2(b3[q]);
                    a[8 + 2 * q]     = fmaf(d0, g0.x, fmaf(d1, g1.x,
                                        fmaf(d2, g2.x, fmaf(d3, g3.x, a[8 + 2 * q]))));
                    a[8 + 2 * q + 1] = fmaf(d0, g0.y, fmaf(d1, g1.y,
                                        fmaf(d2, g2.y, fmaf(d3, g3.y, a[8 + 2 * q + 1]))));
                }
            }
            while (e < end) { acc1(Hin, __ldg(&g_csr[e]), sub, a); e++; }

            #pragma unroll
            for (int q = 0; q < 16; q++) {
                float o = fmaxf(fmaf(dv, a[q], bias_g[sub * 16 + q]), 0.f);
                split_bf16(o, hs[q], ls[q]);
            }
        } else {
            #pragma unroll
            for (int q = 0; q < 16; q++) { hs[q] = 0; ls[q] = 0; }
        }
        uint32_t off = (uint32_t)((tid >> 2) * HSTR + sub * 16) * 2;
        #pragma unroll
        for (int q = 0; q < 4; q++) {
            *(ushort4*)(smem + F_AH + off + q * 8) =
                make_ushort4(hs[4 * q], hs[4 * q + 1], hs[4 * q + 2], hs[4 * q + 3]);
            *(ushort4*)(smem + F_AL + off + q * 8) =
                make_ushort4(ls[4 * q], ls[4 * q + 1], ls[4 * q + 2], ls[4 * q + 3]);
        }
    }

    // ---- phase 2: B fill (pure copy of pre-split planes) ----
    #pragma unroll
    for (int i = 0; i < 2; i++) {
        int idx = tid + i * 256;               // uint4 index (512 total)
        int n = idx >> 3, k = (idx & 7) * 8;
        uint32_t off = (uint32_t)(n * HSTR + k) * 2;
        *(uint4*)(smem + F_BH + off) = ((const uint4*)Wh)[idx];
        *(uint4*)(smem + F_BL + off) = ((const uint4*)Wl)[idx];
    }
    __syncthreads();

    // ---- phase 3: mma (8 warps: 4 row-groups x 2 col-groups) ----
    const int wid  = tid >> 5;
    const int lane = tid & 31;
    const uint32_t sb = smem_u32(smem);
    const int rw = (wid & 3) * 16;
    const int cw = (wid >> 2) * 32;
    const int li = lane >> 3;
    const int lw = lane & 7;
    const uint32_t a_off =
        (uint32_t)(((rw + (li & 1) * 8 + lw) * HSTR + (li >> 1) * 8) * 2);
    const uint32_t b_off =
        (uint32_t)((((li >> 1) * 8 + lw) * HSTR + (li & 1) * 8) * 2);

    float acc[4][4];
    #pragma unroll
    for (int nt = 0; nt < 4; nt++)
        #pragma unroll
        for (int q = 0; q < 4; q++) acc[nt][q] = 0.f;

    const uint32_t aB[3] = { sb + F_AH, sb + F_AH, sb + F_AL };
    const uint32_t bB[3] = { sb + F_BH, sb + F_BL, sb + F_BH };
    #pragma unroll
    for (int pass = 0; pass < 3; pass++) {
        #pragma unroll
        for (int kt = 0; kt < 4; kt++) {
            uint32_t a[4];
            ldsm4(a[0], a[1], a[2], a[3], aB[pass] + a_off + kt * 32);
            #pragma unroll
            for (int ntp = 0; ntp < 2; ntp++) {
                uint32_t b0, b1, b2, b3;
                ldsm4(b0, b1, b2, b3,
                      bB[pass] + b_off + (uint32_t)((cw + ntp * 16) * HSTR * 2) + kt * 32);
                mma16816(acc[2 * ntp],     a, b0, b1);
                mma16816(acc[2 * ntp + 1], a, b2, b3);
            }
        }
    }

    // ---- epilogue ----
    const int rA = rw + (lane >> 2);
    long long gA = base + rA, gB = gA + 8;
    bool vA = gA < NN, vB = gB < NN;
    #pragma unroll
    for (int nt = 0; nt < 4; nt++) {
        int cg = cw + nt * 8 + (lane & 3) * 2;
        if (Hout) {
            if (vA) *(__half2*)&Hout[gA * 64 + cg] =
                __floats2half2_rn(acc[nt][0], acc[nt][1]);
            if (vB) *(__half2*)&Hout[gB * 64 + cg] =
                __floats2half2_rn(acc[nt][2], acc[nt][3]);
        } else {
            float bx = bias_f[cg], by = bias_f[cg + 1];
            if (vA) {
                float2 o = make_float2(acc[nt][0] + bx, acc[nt][1] + by);
                *(float2*)&Fout[gA * 64 + cg] = o;
            }
            if (vB) {
                float2 o = make_float2(acc[nt][2] + bx, acc[nt][3] + by);
                *(float2*)&Fout[gB * 64 + cg] = o;
            }
        }
    }
}

// ---------------------------------------------------------------------------
extern "C" void kernel_launch(void* const* d_in, const int* in_sizes, int n_in,
                              void* d_out, int out_size) {
    const float* x    = (const float*)d_in[0];
    const void*  ei   = d_in[1];
    const float* Ws   = (const float*)d_in[2];
    const float* bs   = (const float*)d_in[3];
    const float* Wout = (const float*)d_in[4];
    const float* bout = (const float*)d_in[5];
    float* out = (float*)d_out;

    uint4 *hA, *hB;
    unsigned short *wh, *wl;
    cudaGetSymbolAddress((void**)&hA, g_hA);
    cudaGetSymbolAddress((void**)&hB, g_hB);
    cudaGetSymbolAddress((void**)&wh, g_wh);
    cudaGetSymbolAddress((void**)&wl, g_wl);

    cudaFuncSetAttribute(gemm_f32, cudaFuncAttributeMaxDynamicSharedMemorySize, G_TOT);
    cudaFuncSetAttribute(fused_gg, cudaFuncAttributeMaxDynamicSharedMemorySize, F_TOT);

    // Side stream + events, created once on the (uncaptured) correctness call.
    static cudaStream_t s2 = nullptr;
    static cudaEvent_t  ev_fork = nullptr, ev_g1 = nullptr;
    if (!s2) {
        cudaStreamCreateWithFlags(&s2, cudaStreamNonBlocking);
        cudaEventCreateWithFlags(&ev_fork, cudaEventDisableTiming);
        cudaEventCreateWithFlags(&ev_g1, cudaEventDisableTiming);
    }

    const int GB_E  = (NE + 255) / 256;
    const int GB_N  = (NN + 255) / 256;
    const int GB_MM = (NN + 127) / 128;
    const int GB_F  = (NN + 63) / 64;

    // Fork: GEMM-1 + weight-plane conversion (input-only deps) run on s2.
    cudaEventRecord(ev_fork, 0);
    cudaStreamWaitEvent(s2, ev_fork, 0);
    gemm_f32<<<GB_MM, 256, G_TOT, s2>>>(x, Ws, (__half*)hA);
    wconv<<<48, 256, 0, s2>>>(Ws, Wout);
    cudaEventRecord(ev_g1, s2);

    // CSR build on the main stream.
    degi_count<<<GB_E, 256>>>(ei);
    scan1<<<NSCB, SCAN_T>>>();
    scan23<<<GB_N, 256>>>();
    csr_fill<<<GB_E, 256>>>(ei);

    // Join, then 3 fused gather+gemm stages (ping-pong h buffers).
    cudaStreamWaitEvent(0, ev_g1, 0);
    fused_gg<<<GB_F, 256, F_TOT>>>(hA, bs,         wh,        wl,        (__half*)hB, nullptr, nullptr);
    fused_gg<<<GB_F, 256, F_TOT>>>(hB, bs + D,     wh + 4096, wl + 4096, (__half*)hA, nullptr, nullptr);
    fused_gg<<<GB_F, 256, F_TOT>>>(hA, bs + 2 * D, wh + 8192, wl + 8192, nullptr, out, bout);
}

// round 15
// speedup vs baseline: 1.0186x; 1.0186x over previous
#include <cuda_runtime.h>
#include <cuda_bf16.h>
#include <cuda_fp16.h>
#include <cstdint>

static constexpr int NN = 100000;   // nodes
static constexpr int D  = 64;       // feature dim
static constexpr int NE = 1000000;  // edges

static constexpr int SCAN_T = 512;
static constexpr int NSCB   = (NN + SCAN_T - 1) / SCAN_T;   // 196

// Scratch (device globals — no allocation allowed)
__device__ uint4          g_hA[NN * 8];   // h fp16 ping (64 halves = 8 uint4/row)
__device__ uint4          g_hB[NN * 8];   // h fp16 pong
__device__ unsigned short g_wh[3 * 4096]; // W planes hi, [n*64+k], layers {1,2,out}
__device__ unsigned short g_wl[3 * 4096]; // W planes lo
__device__ float g_dinv[NN];
__device__ int   g_degi[NN];      // zero at entry (BSS first call; csr_fill re-zeros)
__device__ int   g_off [NN + 1];
__device__ int   g_cur [NN];
__device__ int   g_scan[NN];
__device__ int   g_bsum[NSCB];
__device__ int   g_csr [NE];      // src ids grouped by dst

// ---------------------------------------------------------------------------
// Per-block int64-vs-int32 detection (JAX may silently downcast edge_index).
__device__ __forceinline__ int block_detect64(const int* __restrict__ w) {
    __shared__ int s_flag;
    if (threadIdx.x == 0) s_flag = 0;
    __syncthreads();
    if (threadIdx.x < 64 && w[2 * threadIdx.x + 1]) atomicOr(&s_flag, 1);
    __syncthreads();
    return s_flag == 0;
}

__device__ __forceinline__ int edge_at(const void* ei, int is64, long long pos) {
    if (is64) return (int)((const long long*)ei)[pos];
    return ((const int*)ei)[pos];
}

__global__ void degi_count(const void* __restrict__ ei) {
    int is64 = block_detect64((const int*)ei);
    int e = blockIdx.x * 256 + threadIdx.x;
    if (e < NE) atomicAdd(&g_degi[edge_at(ei, is64, (long long)NE + e)], 1);
}

// ---- prefix scans (warp-shuffle based) ------------------------------------
__global__ void scan1() {
    int i = blockIdx.x * SCAN_T + threadIdx.x;
    int lane = threadIdx.x & 31, w = threadIdx.x >> 5;
    int s = (i < NN) ? g_degi[i] : 0;
    #pragma unroll
    for (int off = 1; off < 32; off <<= 1) {
        int t = __shfl_up_sync(0xFFFFFFFFu, s, off);
        if (lane >= off) s += t;
    }
    __shared__ int wsum[16];
    if (lane == 31) wsum[w] = s;
    __syncthreads();
    if (w == 0) {
        int t = (lane < 16) ? wsum[lane] : 0;
        #pragma unroll
        for (int off = 1; off < 16; off <<= 1) {
            int u = __shfl_up_sync(0xFFFFFFFFu, t, off);
            if (lane >= off) t += u;
        }
        if (lane < 16) wsum[lane] = t;
    }
    __syncthreads();
    int incl = s + (w > 0 ? wsum[w - 1] : 0);
    if (i < NN) g_scan[i] = incl;
    if (threadIdx.x == SCAN_T - 1) g_bsum[blockIdx.x] = incl;
}

// Fused: shuffle-scan of the 196 block sums + offsets + cursor + dinv.
__global__ void scan23() {
    __shared__ int bsx[256];
    {
        int lane = threadIdx.x & 31, w = threadIdx.x >> 5;
        int s = (threadIdx.x < NSCB) ? g_bsum[threadIdx.x] : 0;
        #pragma unroll
        for (int off = 1; off < 32; off <<= 1) {
            int t = __shfl_up_sync(0xFFFFFFFFu, s, off);
            if (lane >= off) s += t;
        }
        __shared__ int wsum[8];
        if (lane == 31) wsum[w] = s;
        __syncthreads();
        if (w == 0 && lane < 8) {
            int t = wsum[lane];
            #pragma unroll
            for (int off = 1; off < 8; off <<= 1) {
                int u = __shfl_up_sync(0xFFu, t, off);
                if (lane >= off) t += u;
            }
            wsum[lane] = t;
        }
        __syncthreads();
        bsx[threadIdx.x] = s + (w > 0 ? wsum[w - 1] : 0);
    }
    __syncthreads();
    int i = blockIdx.x * 256 + threadIdx.x;
    if (i >= NN) return;
    int b  = i / SCAN_T;
    int di = g_degi[i];
    int incl = g_scan[i] + (b > 0 ? bsx[b - 1] : 0);
    g_off[i + 1] = incl;
    if (i == 0) g_off[0] = 0;
    g_cur[i] = incl - di;
    g_dinv[i] = rsqrtf(1.0f + (float)di);
}

// Fill CSR; also re-zero g_degi so the NEXT invocation starts clean.
__global__ void csr_fill(const void* __restrict__ ei) {
    int is64 = block_detect64((const int*)ei);
    int e = blockIdx.x * 256 + threadIdx.x;
    if (e < NN) g_degi[e] = 0;
    if (e >= NE) return;
    int src = edge_at(ei, is64, e);
    int dst = edge_at(ei, is64, (long long)NE + e);
    int pos = atomicAdd(&g_cur[dst], 1);
    g_csr[pos] = src;
}

// ---------------------------------------------------------------------------
__device__ __forceinline__ void split_bf16(float x, unsigned short& h, unsigned short& l) {
    __nv_bfloat16 hb = __float2bfloat16(x);
    __nv_bfloat16 lb = __float2bfloat16(x - __bfloat162float(hb));
    h = __bfloat16_as_ushort(hb);
    l = __bfloat16_as_ushort(lb);
}

// Pre-split W planes for layers {1,2,out}: [n*64+k] hi/lo from row-major W[k][n].
__global__ void wconv(const float* __restrict__ Ws, const float* __restrict__ Wout) {
    int idx = blockIdx.x * 256 + threadIdx.x;     // 0 .. 3*4096
    if (idx >= 3 * 4096) return;
    int l   = idx >> 12;
    int rem = idx & 4095;
    int k = rem >> 6, n = rem & 63;
    float v = (l < 2) ? Ws[(l + 1) * 4096 + rem] : Wout[rem];
    unsigned short h, lo;
    split_bf16(v, h, lo);
    g_wh[l * 4096 + n * 64 + k] = h;
    g_wl[l * 4096 + n * 64 + k] = lo;
}

// ---------------------------------------------------------------------------
// Tensor-core machinery (mma.sync bf16, 3-pass compensation).
static constexpr int HSTR  = 72;   // halves per row (64 + 8 pad)

__device__ __forceinline__ uint32_t smem_u32(const void* p) {
    uint32_t a;
    asm("{ .reg .u64 t; cvta.to.shared.u64 t, %1; cvt.u32.u64 %0, t; }"
        : "=r"(a) : "l"(p));
    return a;
}
__device__ __forceinline__ void ldsm4(uint32_t& r0, uint32_t& r1, uint32_t& r2,
                                      uint32_t& r3, uint32_t addr) {
    asm volatile("ldmatrix.sync.aligned.m8n8.x4.shared.b16 {%0,%1,%2,%3}, [%4];"
                 : "=r"(r0), "=r"(r1), "=r"(r2), "=r"(r3) : "r"(addr));
}
__device__ __forceinline__ void mma16816(float* c, const uint32_t* a,
                                         uint32_t b0, uint32_t b1) {
    asm volatile(
        "mma.sync.aligned.m16n8k16.row.col.f32.bf16.bf16.f32 "
        "{%0,%1,%2,%3}, {%4,%5,%6,%7}, {%8,%9}, {%0,%1,%2,%3};"
        : "+f"(c[0]), "+f"(c[1]), "+f"(c[2]), "+f"(c[3])
        : "r"(a[0]), "r"(a[1]), "r"(a[2]), "r"(a[3]), "r"(b0), "r"(b1));
}

// ======================= Layer-1 GEMM (128-row tile) =======================
static constexpr int G_AH = 0;
static constexpr int G_AL = G_AH + 128 * HSTR * 2;   // 18432
static constexpr int G_BH = G_AL + 128 * HSTR * 2;   // 36864
static constexpr int G_BL = G_BH + 64 * HSTR * 2;    // 46080
static constexpr int G_TOT = G_BL + 64 * HSTR * 2;   // 55296

__global__ void __launch_bounds__(256) gemm_f32(
        const float* __restrict__ X, const float* __restrict__ W,
        __half* __restrict__ Yh) {
    extern __shared__ char smem[];
    const int tid  = threadIdx.x;
    const long long base = (long long)blockIdx.x * 128;

    #pragma unroll
    for (int i = 0; i < 8; i++) {
        int idx  = tid + i * 256;
        int row  = idx >> 4;
        int k    = (idx & 15) * 4;
        float4 v = make_float4(0.f, 0.f, 0.f, 0.f);
        if (base + row < NN)
            v = ((const float4*)X)[(base + row) * 16 + (k >> 2)];
        unsigned short h0, l0, h1, l1, h2v, l2v, h3, l3;
        split_bf16(v.x, h0, l0); split_bf16(v.y, h1, l1);
        split_bf16(v.z, h2v, l2v); split_bf16(v.w, h3, l3);
        unsigned long long hp = (unsigned long long)h0
            | ((unsigned long long)h1 << 16) | ((unsigned long long)h2v << 32)
            | ((unsigned long long)h3 << 48);
        unsigned long long lp = (unsigned long long)l0
            | ((unsigned long long)l1 << 16) | ((unsigned long long)l2v << 32)
            | ((unsigned long long)l3 << 48);
        uint32_t off = (uint32_t)(row * HSTR + k) * 2;
        *(unsigned long long*)(smem + G_AH + off) = hp;
        *(unsigned long long*)(smem + G_AL + off) = lp;
    }
    #pragma unroll
    for (int i = 0; i < 16; i++) {
        int idx = tid + i * 256;
        int k = idx >> 6, n = idx & 63;
        unsigned short h, l;
        split_bf16(W[idx], h, l);
        uint32_t off = (uint32_t)(n * HSTR + k) * 2;
        *(unsigned short*)(smem + G_BH + off) = h;
        *(unsigned short*)(smem + G_BL + off) = l;
    }
    __syncthreads();

    const int wid  = tid >> 5;
    const int lane = tid & 31;
    const uint32_t sb = smem_u32(smem);
    const int r0w = wid * 16;
    const int li  = lane >> 3;
    const int lw  = lane & 7;
    const uint32_t a_off =
        (uint32_t)(((r0w + (li & 1) * 8 + lw) * HSTR + (li >> 1) * 8) * 2);
    const uint32_t b_off =
        (uint32_t)((((li >> 1) * 8 + lw) * HSTR + (li & 1) * 8) * 2);

    float acc[8][4];
    #pragma unroll
    for (int nt = 0; nt < 8; nt++)
        #pragma unroll
        for (int q = 0; q < 4; q++) acc[nt][q] = 0.f;

    const uint32_t aB[3] = { sb + G_AH, sb + G_AH, sb + G_AL };
    const uint32_t bB[3] = { sb + G_BH, sb + G_BL, sb + G_BH };
    #pragma unroll
    for (int pass = 0; pass < 3; pass++) {
        #pragma unroll
        for (int kt = 0; kt < 4; kt++) {
            uint32_t a[4];
            ldsm4(a[0], a[1], a[2], a[3], aB[pass] + a_off + kt * 32);
            #pragma unroll
            for (int ntp = 0; ntp < 4; ntp++) {
                uint32_t b0, b1, b2, b3;
                ldsm4(b0, b1, b2, b3,
                      bB[pass] + b_off + (uint32_t)(ntp * 16 * HSTR * 2) + kt * 32);
                mma16816(acc[2 * ntp],     a, b0, b1);
                mma16816(acc[2 * ntp + 1], a, b2, b3);
            }
        }
    }

    const int rA = r0w + (lane >> 2);
    long long gA = base + rA, gB = gA + 8;
    bool vA = gA < NN, vB = gB < NN;
    #pragma unroll
    for (int nt = 0; nt < 8; nt++) {
        int cg = nt * 8 + (lane & 3) * 2;
        if (vA) *(__half2*)&Yh[gA * 64 + cg] = __floats2half2_rn(acc[nt][0], acc[nt][1]);
        if (vB) *(__half2*)&Yh[gB * 64 + cg] = __floats2half2_rn(acc[nt][2], acc[nt][3]);
    }
}

// ======================= Fused gather + GEMM (64-row tile) =================
static constexpr int F_AH = 0;
static constexpr int F_AL = F_AH + 64 * HSTR * 2;    // 9216
static constexpr int F_BH = F_AL + 64 * HSTR * 2;    // 18432
static constexpr int F_BL = F_BH + 64 * HSTR * 2;    // 27648
static constexpr int F_EDG = F_BL + 64 * HSTR * 2;   // 36864 (staged edge list)
static constexpr int ECAP  = 1280;                   // ints (Poisson(640), >20 sigma)
static constexpr int F_TOT = F_EDG + ECAP * 4;       // 41984

// Gather layer activations for 64 nodes straight into smem bf16 planes
// (4 threads/node, 16 cols each; tile edge list staged in smem so the
// dependent chain per edge-pair is LDS(idx) -> LDG(H), not LDG -> LDG),
// then multiply by pre-split W planes.
__global__ void __launch_bounds__(256) fused_gg(
        const uint4* __restrict__ Hin, const float* __restrict__ bias_g,
        const unsigned short* __restrict__ Wh, const unsigned short* __restrict__ Wl,
        __half* __restrict__ Hout, float* __restrict__ Fout,
        const float* __restrict__ bias_f) {
    extern __shared__ char smem[];
    const int tid  = threadIdx.x;
    const long long base = (long long)blockIdx.x * 64;
    int* s_edge = (int*)(smem + F_EDG);

    // ---- phase 0: stage this tile's contiguous CSR slice into smem ----
    const int e0 = g_off[base];
    const int e1 = g_off[(base + 64 < NN) ? (base + 64) : NN];
    const int cnt = min(e1 - e0, ECAP);
    for (int i = tid; i < cnt; i += 256) s_edge[i] = g_csr[e0 + i];

    // ---- phase 0b: B fill (independent; overlaps the staging/gather) ----
    #pragma unroll
    for (int i = 0; i < 2; i++) {
        int idx = tid + i * 256;               // uint4 index (512 total)
        int n = idx >> 3, k = (idx & 7) * 8;
        uint32_t off = (uint32_t)(n * HSTR + k) * 2;
        *(uint4*)(smem + F_BH + off) = ((const uint4*)Wh)[idx];
        *(uint4*)(smem + F_BL + off) = ((const uint4*)Wl)[idx];
    }
    __syncthreads();

    // ---- phase 1: gather (4 threads per node, 16 cols each) ----
    {
        int node = (int)base + (tid >> 2);
        int sub  = tid & 3;
        unsigned short hs[16], ls[16];
        if (node < NN) {
            float dv = g_dinv[node];
            float a[16];
            {
                uint4 v0 = Hin[node * 8 + sub * 2];
                uint4 v1 = Hin[node * 8 + sub * 2 + 1];
                const __half2* p0 = (const __half2*)&v0;
                const __half2* p1 = (const __half2*)&v1;
                #pragma unroll
                for (int q = 0; q < 4; q++) {
                    float2 f0 = __half22float2(p0[q]);
                    float2 f1 = __half22float2(p1[q]);
                    a[2 * q]      = dv * f0.x;
                    a[2 * q + 1]  = dv * f0.y;
                    a[8 + 2 * q]     = dv * f1.x;
                    a[8 + 2 * q + 1] = dv * f1.y;
                }
            }
            int e   = g_off[node] - e0;          // local edge index
            int end = g_off[node + 1] - e0;
            for (; e + 1 < end; e += 2) {
                int s0 = (e     < cnt) ? s_edge[e]     : __ldg(&g_csr[e0 + e]);
                int s1 = (e + 1 < cnt) ? s_edge[e + 1] : __ldg(&g_csr[e0 + e + 1]);
                float d0 = g_dinv[s0], d1 = g_dinv[s1];
                uint4 u0 = Hin[s0 * 8 + sub * 2];
                uint4 u1 = Hin[s0 * 8 + sub * 2 + 1];
                uint4 w0 = Hin[s1 * 8 + sub * 2];
                uint4 w1 = Hin[s1 * 8 + sub * 2 + 1];
                const __half2* q0 = (const __half2*)&u0;
                const __half2* q1 = (const __half2*)&u1;
                const __half2* r0 = (const __half2*)&w0;
                const __half2* r1 = (const __half2*)&w1;
                #pragma unroll
                for (int q = 0; q < 4; q++) {
                    float2 f0 = __half22float2(q0[q]);
                    float2 g0 = __half22float2(r0[q]);
                    a[2 * q]     = fmaf(d0, f0.x, fmaf(d1, g0.x, a[2 * q]));
                    a[2 * q + 1] = fmaf(d0, f0.y, fmaf(d1, g0.y, a[2 * q + 1]));
                    float2 f1 = __half22float2(q1[q]);
                    float2 g1 = __half22float2(r1[q]);
                    a[8 + 2 * q]     = fmaf(d0, f1.x, fmaf(d1, g1.x, a[8 + 2 * q]));
                    a[8 + 2 * q + 1] = fmaf(d0, f1.y, fmaf(d1, g1.y, a[8 + 2 * q + 1]));
                }
            }
            if (e < end) {
                int s0 = (e < cnt) ? s_edge[e] : __ldg(&g_csr[e0 + e]);
                float d0 = g_dinv[s0];
                uint4 u0 = Hin[s0 * 8 + sub * 2];
                uint4 u1 = Hin[s0 * 8 + sub * 2 + 1];
                const __half2* q0 = (const __half2*)&u0;
                const __half2* q1 = (const __half2*)&u1;
                #pragma unroll
                for (int q = 0; q < 4; q++) {
                    float2 f0 = __half22float2(q0[q]);
                    a[2 * q]     = fmaf(d0, f0.x, a[2 * q]);
                    a[2 * q + 1] = fmaf(d0, f0.y, a[2 * q + 1]);
                    float2 f1 = __half22float2(q1[q]);
                    a[8 + 2 * q]     = fmaf(d0, f1.x, a[8 + 2 * q]);
                    a[8 + 2 * q + 1] = fmaf(d0, f1.y, a[8 + 2 * q + 1]);
                }
            }
            #pragma unroll
            for (int q = 0; q < 16; q++) {
                float o = fmaxf(fmaf(dv, a[q], bias_g[sub * 16 + q]), 0.f);
                split_bf16(o, hs[q], ls[q]);
            }
        } else {
            #pragma unroll
            for (int q = 0; q < 16; q++) { hs[q] = 0; ls[q] = 0; }
        }
        uint32_t off = (uint32_t)((tid >> 2) * HSTR + sub * 16) * 2;
        #pragma unroll
        for (int q = 0; q < 4; q++) {
            *(ushort4*)(smem + F_AH + off + q * 8) =
                make_ushort4(hs[4 * q], hs[4 * q + 1], hs[4 * q + 2], hs[4 * q + 3]);
            *(ushort4*)(smem + F_AL + off + q * 8) =
                make_ushort4(ls[4 * q], ls[4 * q + 1], ls[4 * q + 2], ls[4 * q + 3]);
        }
    }
    __syncthreads();

    // ---- phase 2: mma (8 warps: 4 row-groups x 2 col-groups) ----
    const int wid  = tid >> 5;
    const int lane = tid & 31;
    const uint32_t sb = smem_u32(smem);
    const int rw = (wid & 3) * 16;
    const int cw = (wid >> 2) * 32;
    const int li = lane >> 3;
    const int lw = lane & 7;
    const uint32_t a_off =
        (uint32_t)(((rw + (li & 1) * 8 + lw) * HSTR + (li >> 1) * 8) * 2);
    const uint32_t b_off =
        (uint32_t)((((li >> 1) * 8 + lw) * HSTR + (li & 1) * 8) * 2);

    float acc[4][4];
    #pragma unroll
    for (int nt = 0; nt < 4; nt++)
        #pragma unroll
        for (int q = 0; q < 4; q++) acc[nt][q] = 0.f;

    const uint32_t aB[3] = { sb + F_AH, sb + F_AH, sb + F_AL };
    const uint32_t bB[3] = { sb + F_BH, sb + F_BL, sb + F_BH };
    #pragma unroll
    for (int pass = 0; pass < 3; pass++) {
        #pragma unroll
        for (int kt = 0; kt < 4; kt++) {
            uint32_t a[4];
            ldsm4(a[0], a[1], a[2], a[3], aB[pass] + a_off + kt * 32);
            #pragma unroll
            for (int ntp = 0; ntp < 2; ntp++) {
                uint32_t b0, b1, b2, b3;
                ldsm4(b0, b1, b2, b3,
                      bB[pass] + b_off + (uint32_t)((cw + ntp * 16) * HSTR * 2) + kt * 32);
                mma16816(acc[2 * ntp],     a, b0, b1);
                mma16816(acc[2 * ntp + 1], a, b2, b3);
            }
        }
    }

    // ---- epilogue ----
    const int rA = rw + (lane >> 2);
    long long gA = base + rA, gB = gA + 8;
    bool vA = gA < NN, vB = gB < NN;
    #pragma unroll
    for (int nt = 0; nt < 4; nt++) {
        int cg = cw + nt * 8 + (lane & 3) * 2;
        if (Hout) {
            if (vA) *(__half2*)&Hout[gA * 64 + cg] =
                __floats2half2_rn(acc[nt][0], acc[nt][1]);
            if (vB) *(__half2*)&Hout[gB * 64 + cg] =
                __floats2half2_rn(acc[nt][2], acc[nt][3]);
        } else {
            float bx = bias_f[cg], by = bias_f[cg + 1];
            if (vA) {
                float2 o = make_float2(acc[nt][0] + bx, acc[nt][1] + by);
                *(float2*)&Fout[gA * 64 + cg] = o;
            }
            if (vB) {
                float2 o = make_float2(acc[nt][2] + bx, acc[nt][3] + by);
                *(float2*)&Fout[gB * 64 + cg] = o;
            }
        }
    }
}

// ---------------------------------------------------------------------------
extern "C" void kernel_launch(void* const* d_in, const int* in_sizes, int n_in,
                              void* d_out, int out_size) {
    const float* x    = (const float*)d_in[0];
    const void*  ei   = d_in[1];
    const float* Ws   = (const float*)d_in[2];
    const float* bs   = (const float*)d_in[3];
    const float* Wout = (const float*)d_in[4];
    const float* bout = (const float*)d_in[5];
    float* out = (float*)d_out;

    uint4 *hA, *hB;
    unsigned short *wh, *wl;
    cudaGetSymbolAddress((void**)&hA, g_hA);
    cudaGetSymbolAddress((void**)&hB, g_hB);
    cudaGetSymbolAddress((void**)&wh, g_wh);
    cudaGetSymbolAddress((void**)&wl, g_wl);

    cudaFuncSetAttribute(gemm_f32, cudaFuncAttributeMaxDynamicSharedMemorySize, G_TOT);
    cudaFuncSetAttribute(fused_gg, cudaFuncAttributeMaxDynamicSharedMemorySize, F_TOT);

    // Side stream + events, created once on the (uncaptured) correctness call.
    static cudaStream_t s2 = nullptr;
    static cudaEvent_t  ev_fork = nullptr, ev_g1 = nullptr;
    if (!s2) {
        cudaStreamCreateWithFlags(&s2, cudaStreamNonBlocking);
        cudaEventCreateWithFlags(&ev_fork, cudaEventDisableTiming);
        cudaEventCreateWithFlags(&ev_g1, cudaEventDisableTiming);
    }

    const int GB_E  = (NE + 255) / 256;
    const int GB_N  = (NN + 255) / 256;
    const int GB_MM = (NN + 127) / 128;
    const int GB_F  = (NN + 63) / 64;

    // Fork: GEMM-1 + weight-plane conversion (input-only deps) run on s2.
    cudaEventRecord(ev_fork, 0);
    cudaStreamWaitEvent(s2, ev_fork, 0);
    gemm_f32<<<GB_MM, 256, G_TOT, s2>>>(x, Ws, (__half*)hA);
    wconv<<<48, 256, 0, s2>>>(Ws, Wout);
    cudaEventRecord(ev_g1, s2);

    // CSR build on the main stream.
    degi_count<<<GB_E, 256>>>(ei);
    scan1<<<NSCB, SCAN_T>>>();
    scan23<<<GB_N, 256>>>();
    csr_fill<<<GB_E, 256>>>(ei);

    // Join, then 3 fused gather+gemm stages (ping-pong h buffers).
    cudaStreamWaitEvent(0, ev_g1, 0);
    fused_gg<<<GB_F, 256, F_TOT>>>(hA, bs,         wh,        wl,        (__half*)hB, nullptr, nullptr);
    fused_gg<<<GB_F, 256, F_TOT>>>(hB, bs + D,     wh + 4096, wl + 4096, (__half*)hA, nullptr, nullptr);
    fused_gg<<<GB_F, 256, F_TOT>>>(hA, bs + 2 * D, wh + 8192, wl + 8192, nullptr, out, bout);
}

// round 16
// speedup vs baseline: 1.0848x; 1.0649x over previous
#include <cuda_runtime.h>
#include <cuda_bf16.h>
#include <cuda_fp16.h>
#include <cstdint>

static constexpr int NN = 100000;   // nodes
static constexpr int D  = 64;       // feature dim
static constexpr int NE = 1000000;  // edges

static constexpr int SCAN_T = 512;
static constexpr int NSCB   = (NN + SCAN_T - 1) / SCAN_T;   // 196

// Scratch (device globals — no allocation allowed)
__device__ uint4          g_hA[NN * 8];   // h fp16 ping (64 halves = 8 uint4/row)
__device__ uint4          g_hB[NN * 8];   // h fp16 pong
__device__ unsigned short g_wh[3 * 4096]; // W planes hi (fp16), [n*64+k], layers {1,2,out}
__device__ unsigned short g_wl[3 * 4096]; // W planes lo (fp16 residual)
__device__ float g_dinv[NN];
__device__ int   g_degi[NN];      // zero at entry (BSS first call; csr_fill re-zeros)
__device__ int   g_off [NN + 1];
__device__ int   g_cur [NN];
__device__ int   g_scan[NN];
__device__ int   g_bsum[NSCB];
__device__ int   g_csr [NE];      // src ids grouped by dst

// ---------------------------------------------------------------------------
// Per-block int64-vs-int32 detection (JAX may silently downcast edge_index).
__device__ __forceinline__ int block_detect64(const int* __restrict__ w) {
    __shared__ int s_flag;
    if (threadIdx.x == 0) s_flag = 0;
    __syncthreads();
    if (threadIdx.x < 64 && w[2 * threadIdx.x + 1]) atomicOr(&s_flag, 1);
    __syncthreads();
    return s_flag == 0;
}

__device__ __forceinline__ int edge_at(const void* ei, int is64, long long pos) {
    if (is64) return (int)((const long long*)ei)[pos];
    return ((const int*)ei)[pos];
}

__global__ void degi_count(const void* __restrict__ ei) {
    int is64 = block_detect64((const int*)ei);
    int e = blockIdx.x * 256 + threadIdx.x;
    if (e < NE) atomicAdd(&g_degi[edge_at(ei, is64, (long long)NE + e)], 1);
}

// ---- prefix scans (warp-shuffle based) ------------------------------------
__global__ void scan1() {
    int i = blockIdx.x * SCAN_T + threadIdx.x;
    int lane = threadIdx.x & 31, w = threadIdx.x >> 5;
    int s = (i < NN) ? g_degi[i] : 0;
    #pragma unroll
    for (int off = 1; off < 32; off <<= 1) {
        int t = __shfl_up_sync(0xFFFFFFFFu, s, off);
        if (lane >= off) s += t;
    }
    __shared__ int wsum[16];
    if (lane == 31) wsum[w] = s;
    __syncthreads();
    if (w == 0) {
        int t = (lane < 16) ? wsum[lane] : 0;
        #pragma unroll
        for (int off = 1; off < 16; off <<= 1) {
            int u = __shfl_up_sync(0xFFFFFFFFu, t, off);
            if (lane >= off) t += u;
        }
        if (lane < 16) wsum[lane] = t;
    }
    __syncthreads();
    int incl = s + (w > 0 ? wsum[w - 1] : 0);
    if (i < NN) g_scan[i] = incl;
    if (threadIdx.x == SCAN_T - 1) g_bsum[blockIdx.x] = incl;
}

// Fused: shuffle-scan of the 196 block sums + offsets + cursor + dinv.
__global__ void scan23() {
    __shared__ int bsx[256];
    {
        int lane = threadIdx.x & 31, w = threadIdx.x >> 5;
        int s = (threadIdx.x < NSCB) ? g_bsum[threadIdx.x] : 0;
        #pragma unroll
        for (int off = 1; off < 32; off <<= 1) {
            int t = __shfl_up_sync(0xFFFFFFFFu, s, off);
            if (lane >= off) s += t;
        }
        __shared__ int wsum[8];
        if (lane == 31) wsum[w] = s;
        __syncthreads();
        if (w == 0 && lane < 8) {
            int t = wsum[lane];
            #pragma unroll
            for (int off = 1; off < 8; off <<= 1) {
                int u = __shfl_up_sync(0xFFu, t, off);
                if (lane >= off) t += u;
            }
            wsum[lane] = t;
        }
        __syncthreads();
        bsx[threadIdx.x] = s + (w > 0 ? wsum[w - 1] : 0);
    }
    __syncthreads();
    int i = blockIdx.x * 256 + threadIdx.x;
    if (i >= NN) return;
    int b  = i / SCAN_T;
    int di = g_degi[i];
    int incl = g_scan[i] + (b > 0 ? bsx[b - 1] : 0);
    g_off[i + 1] = incl;
    if (i == 0) g_off[0] = 0;
    g_cur[i] = incl - di;
    g_dinv[i] = rsqrtf(1.0f + (float)di);
}

// Fill CSR; also re-zero g_degi so the NEXT invocation starts clean.
__global__ void csr_fill(const void* __restrict__ ei) {
    int is64 = block_detect64((const int*)ei);
    int e = blockIdx.x * 256 + threadIdx.x;
    if (e < NN) g_degi[e] = 0;
    if (e >= NE) return;
    int src = edge_at(ei, is64, e);
    int dst = edge_at(ei, is64, (long long)NE + e);
    int pos = atomicAdd(&g_cur[dst], 1);
    g_csr[pos] = src;
}

// ---------------------------------------------------------------------------
__device__ __forceinline__ void split_bf16(float x, unsigned short& h, unsigned short& l) {
    __nv_bfloat16 hb = __float2bfloat16(x);
    __nv_bfloat16 lb = __float2bfloat16(x - __bfloat162float(hb));
    h = __bfloat16_as_ushort(hb);
    l = __bfloat16_as_ushort(lb);
}
__device__ __forceinline__ void split_f16(float x, unsigned short& h, unsigned short& l) {
    __half hb = __float2half_rn(x);
    __half lb = __float2half_rn(x - __half2float(hb));
    h = __half_as_ushort(hb);
    l = __half_as_ushort(lb);
}

// Pre-split W planes (fp16 hi/lo) for layers {1,2,out}: [n*64+k] from W[k][n].
__global__ void wconv(const float* __restrict__ Ws, const float* __restrict__ Wout) {
    int idx = blockIdx.x * 256 + threadIdx.x;     // 0 .. 3*4096
    if (idx >= 3 * 4096) return;
    int l   = idx >> 12;
    int rem = idx & 4095;
    int k = rem >> 6, n = rem & 63;
    float v = (l < 2) ? Ws[(l + 1) * 4096 + rem] : Wout[rem];
    unsigned short h, lo;
    split_f16(v, h, lo);
    g_wh[l * 4096 + n * 64 + k] = h;
    g_wl[l * 4096 + n * 64 + k] = lo;
}

// ---------------------------------------------------------------------------
// Tensor-core machinery.
static constexpr int HSTR  = 72;   // halves per row (64 + 8 pad)

__device__ __forceinline__ uint32_t smem_u32(const void* p) {
    uint32_t a;
    asm("{ .reg .u64 t; cvta.to.shared.u64 t, %1; cvt.u32.u64 %0, t; }"
        : "=r"(a) : "l"(p));
    return a;
}
__device__ __forceinline__ void ldsm4(uint32_t& r0, uint32_t& r1, uint32_t& r2,
                                      uint32_t& r3, uint32_t addr) {
    asm volatile("ldmatrix.sync.aligned.m8n8.x4.shared.b16 {%0,%1,%2,%3}, [%4];"
                 : "=r"(r0), "=r"(r1), "=r"(r2), "=r"(r3) : "r"(addr));
}
__device__ __forceinline__ void mma16816bf(float* c, const uint32_t* a,
                                           uint32_t b0, uint32_t b1) {
    asm volatile(
        "mma.sync.aligned.m16n8k16.row.col.f32.bf16.bf16.f32 "
        "{%0,%1,%2,%3}, {%4,%5,%6,%7}, {%8,%9}, {%0,%1,%2,%3};"
        : "+f"(c[0]), "+f"(c[1]), "+f"(c[2]), "+f"(c[3])
        : "r"(a[0]), "r"(a[1]), "r"(a[2]), "r"(a[3]), "r"(b0), "r"(b1));
}
__device__ __forceinline__ void mma16816h(float* c, const uint32_t* a,
                                          uint32_t b0, uint32_t b1) {
    asm volatile(
        "mma.sync.aligned.m16n8k16.row.col.f32.f16.f16.f32 "
        "{%0,%1,%2,%3}, {%4,%5,%6,%7}, {%8,%9}, {%0,%1,%2,%3};"
        : "+f"(c[0]), "+f"(c[1]), "+f"(c[2]), "+f"(c[3])
        : "r"(a[0]), "r"(a[1]), "r"(a[2]), "r"(a[3]), "r"(b0), "r"(b1));
}

// ======================= Layer-1 GEMM (128-row tile, bf16 3-pass) ==========
static constexpr int G_AH = 0;
static constexpr int G_AL = G_AH + 128 * HSTR * 2;   // 18432
static constexpr int G_BH = G_AL + 128 * HSTR * 2;   // 36864
static constexpr int G_BL = G_BH + 64 * HSTR * 2;    // 46080
static constexpr int G_TOT = G_BL + 64 * HSTR * 2;   // 55296

__global__ void __launch_bounds__(256) gemm_f32(
        const float* __restrict__ X, const float* __restrict__ W,
        __half* __restrict__ Yh) {
    extern __shared__ char smem[];
    const int tid  = threadIdx.x;
    const long long base = (long long)blockIdx.x * 128;

    #pragma unroll
    for (int i = 0; i < 8; i++) {
        int idx  = tid + i * 256;
        int row  = idx >> 4;
        int k    = (idx & 15) * 4;
        float4 v = make_float4(0.f, 0.f, 0.f, 0.f);
        if (base + row < NN)
            v = ((const float4*)X)[(base + row) * 16 + (k >> 2)];
        unsigned short h0, l0, h1, l1, h2v, l2v, h3, l3;
        split_bf16(v.x, h0, l0); split_bf16(v.y, h1, l1);
        split_bf16(v.z, h2v, l2v); split_bf16(v.w, h3, l3);
        unsigned long long hp = (unsigned long long)h0
            | ((unsigned long long)h1 << 16) | ((unsigned long long)h2v << 32)
            | ((unsigned long long)h3 << 48);
        unsigned long long lp = (unsigned long long)l0
            | ((unsigned long long)l1 << 16) | ((unsigned long long)l2v << 32)
            | ((unsigned long long)l3 << 48);
        uint32_t off = (uint32_t)(row * HSTR + k) * 2;
        *(unsigned long long*)(smem + G_AH + off) = hp;
        *(unsigned long long*)(smem + G_AL + off) = lp;
    }
    #pragma unroll
    for (int i = 0; i < 16; i++) {
        int idx = tid + i * 256;
        int k = idx >> 6, n = idx & 63;
        unsigned short h, l;
        split_bf16(W[idx], h, l);
        uint32_t off = (uint32_t)(n * HSTR + k) * 2;
        *(unsigned short*)(smem + G_BH + off) = h;
        *(unsigned short*)(smem + G_BL + off) = l;
    }
    __syncthreads();

    const int wid  = tid >> 5;
    const int lane = tid & 31;
    const uint32_t sb = smem_u32(smem);
    const int r0w = wid * 16;
    const int li  = lane >> 3;
    const int lw  = lane & 7;
    const uint32_t a_off =
        (uint32_t)(((r0w + (li & 1) * 8 + lw) * HSTR + (li >> 1) * 8) * 2);
    const uint32_t b_off =
        (uint32_t)((((li >> 1) * 8 + lw) * HSTR + (li & 1) * 8) * 2);

    float acc[8][4];
    #pragma unroll
    for (int nt = 0; nt < 8; nt++)
        #pragma unroll
        for (int q = 0; q < 4; q++) acc[nt][q] = 0.f;

    const uint32_t aB[3] = { sb + G_AH, sb + G_AH, sb + G_AL };
    const uint32_t bB[3] = { sb + G_BH, sb + G_BL, sb + G_BH };
    #pragma unroll
    for (int pass = 0; pass < 3; pass++) {
        #pragma unroll
        for (int kt = 0; kt < 4; kt++) {
            uint32_t a[4];
            ldsm4(a[0], a[1], a[2], a[3], aB[pass] + a_off + kt * 32);
            #pragma unroll
            for (int ntp = 0; ntp < 4; ntp++) {
                uint32_t b0, b1, b2, b3;
                ldsm4(b0, b1, b2, b3,
                      bB[pass] + b_off + (uint32_t)(ntp * 16 * HSTR * 2) + kt * 32);
                mma16816bf(acc[2 * ntp],     a, b0, b1);
                mma16816bf(acc[2 * ntp + 1], a, b2, b3);
            }
        }
    }

    const int rA = r0w + (lane >> 2);
    long long gA = base + rA, gB = gA + 8;
    bool vA = gA < NN, vB = gB < NN;
    #pragma unroll
    for (int nt = 0; nt < 8; nt++) {
        int cg = nt * 8 + (lane & 3) * 2;
        if (vA) *(__half2*)&Yh[gA * 64 + cg] = __floats2half2_rn(acc[nt][0], acc[nt][1]);
        if (vB) *(__half2*)&Yh[gB * 64 + cg] = __floats2half2_rn(acc[nt][2], acc[nt][3]);
    }
}

// ======================= Fused gather + GEMM (64-row tile, f16 2-pass) =====
static constexpr int F_A  = 0;                       // single fp16 A plane
static constexpr int F_BH = F_A + 64 * HSTR * 2;     // 9216
static constexpr int F_BL = F_BH + 64 * HSTR * 2;    // 18432
static constexpr int F_TOT = F_BL + 64 * HSTR * 2;   // 27648

// Gather layer activations for 64 nodes straight into a smem fp16 A plane
// (4 threads/node, 16 cols each; R13 edge loop), then 2-pass f16 mma with
// pre-split fp16 W planes: D = A*Wh + A*Wl.
__global__ void __launch_bounds__(256) fused_gg(
        const uint4* __restrict__ Hin, const float* __restrict__ bias_g,
        const unsigned short* __restrict__ Wh, const unsigned short* __restrict__ Wl,
        __half* __restrict__ Hout, float* __restrict__ Fout,
        const float* __restrict__ bias_f) {
    extern __shared__ char smem[];
    const int tid  = threadIdx.x;
    const long long base = (long long)blockIdx.x * 64;

    // ---- phase 0: B fill (pure copy; LDGs in flight during gather) ----
    #pragma unroll
    for (int i = 0; i < 2; i++) {
        int idx = tid + i * 256;               // uint4 index (512 total)
        int n = idx >> 3, k = (idx & 7) * 8;
        uint32_t off = (uint32_t)(n * HSTR + k) * 2;
        *(uint4*)(smem + F_BH + off) = ((const uint4*)Wh)[idx];
        *(uint4*)(smem + F_BL + off) = ((const uint4*)Wl)[idx];
    }

    // ---- phase 1: gather (4 threads per node, 16 cols each) ----
    {
        int node = (int)base + (tid >> 2);
        int sub  = tid & 3;
        unsigned short hs[16];
        if (node < NN) {
            float dv = g_dinv[node];
            float a[16];
            {
                uint4 v0 = Hin[node * 8 + sub * 2];
                uint4 v1 = Hin[node * 8 + sub * 2 + 1];
                const __half2* p0 = (const __half2*)&v0;
                const __half2* p1 = (const __half2*)&v1;
                #pragma unroll
                for (int q = 0; q < 4; q++) {
                    float2 f0 = __half22float2(p0[q]);
                    float2 f1 = __half22float2(p1[q]);
                    a[2 * q]      = dv * f0.x;
                    a[2 * q + 1]  = dv * f0.y;
                    a[8 + 2 * q]     = dv * f1.x;
                    a[8 + 2 * q + 1] = dv * f1.y;
                }
            }
            int e   = g_off[node];
            int end = g_off[node + 1];
            for (; e + 1 < end; e += 2) {
                int s0 = __ldg(&g_csr[e]);
                int s1 = __ldg(&g_csr[e + 1]);
                float d0 = g_dinv[s0], d1 = g_dinv[s1];
                uint4 u0 = Hin[s0 * 8 + sub * 2];
                uint4 u1 = Hin[s0 * 8 + sub * 2 + 1];
                uint4 w0 = Hin[s1 * 8 + sub * 2];
                uint4 w1 = Hin[s1 * 8 + sub * 2 + 1];
                const __half2* q0 = (const __half2*)&u0;
                const __half2* q1 = (const __half2*)&u1;
                const __half2* r0 = (const __half2*)&w0;
                const __half2* r1 = (const __half2*)&w1;
                #pragma unroll
                for (int q = 0; q < 4; q++) {
                    float2 f0 = __half22float2(q0[q]);
                    float2 g0 = __half22float2(r0[q]);
                    a[2 * q]     = fmaf(d0, f0.x, fmaf(d1, g0.x, a[2 * q]));
                    a[2 * q + 1] = fmaf(d0, f0.y, fmaf(d1, g0.y, a[2 * q + 1]));
                    float2 f1 = __half22float2(q1[q]);
                    float2 g1 = __half22float2(r1[q]);
                    a[8 + 2 * q]     = fmaf(d0, f1.x, fmaf(d1, g1.x, a[8 + 2 * q]));
                    a[8 + 2 * q + 1] = fmaf(d0, f1.y, fmaf(d1, g1.y, a[8 + 2 * q + 1]));
                }
            }
            if (e < end) {
                int s0 = __ldg(&g_csr[e]);
                float d0 = g_dinv[s0];
                uint4 u0 = Hin[s0 * 8 + sub * 2];
                uint4 u1 = Hin[s0 * 8 + sub * 2 + 1];
                const __half2* q0 = (const __half2*)&u0;
                const __half2* q1 = (const __half2*)&u1;
                #pragma unroll
                for (int q = 0; q < 4; q++) {
                    float2 f0 = __half22float2(q0[q]);
                    a[2 * q]     = fmaf(d0, f0.x, a[2 * q]);
                    a[2 * q + 1] = fmaf(d0, f0.y, a[2 * q + 1]);
                    float2 f1 = __half22float2(q1[q]);
                    a[8 + 2 * q]     = fmaf(d0, f1.x, a[8 + 2 * q]);
                    a[8 + 2 * q + 1] = fmaf(d0, f1.y, a[8 + 2 * q + 1]);
                }
            }
            #pragma unroll
            for (int q = 0; q < 16; q++) {
                float o = fmaxf(fmaf(dv, a[q], bias_g[sub * 16 + q]), 0.f);
                hs[q] = __half_as_ushort(__float2half_rn(o));
            }
        } else {
            #pragma unroll
            for (int q = 0; q < 16; q++) hs[q] = 0;
        }
        uint32_t off = (uint32_t)((tid >> 2) * HSTR + sub * 16) * 2;
        #pragma unroll
        for (int q = 0; q < 4; q++) {
            *(ushort4*)(smem + F_A + off + q * 8) =
                make_ushort4(hs[4 * q], hs[4 * q + 1], hs[4 * q + 2], hs[4 * q + 3]);
        }
    }
    __syncthreads();

    // ---- phase 2: mma (8 warps: 4 row-groups x 2 col-groups; 2 passes) ----
    const int wid  = tid >> 5;
    const int lane = tid & 31;
    const uint32_t sb = smem_u32(smem);
    const int rw = (wid & 3) * 16;
    const int cw = (wid >> 2) * 32;
    const int li = lane >> 3;
    const int lw = lane & 7;
    const uint32_t a_off =
        (uint32_t)(((rw + (li & 1) * 8 + lw) * HSTR + (li >> 1) * 8) * 2);
    const uint32_t b_off =
        (uint32_t)((((li >> 1) * 8 + lw) * HSTR + (li & 1) * 8) * 2);

    float acc[4][4];
    #pragma unroll
    for (int nt = 0; nt < 4; nt++)
        #pragma unroll
        for (int q = 0; q < 4; q++) acc[nt][q] = 0.f;

    const uint32_t bB[2] = { sb + F_BH, sb + F_BL };
    #pragma unroll
    for (int pass = 0; pass < 2; pass++) {
        #pragma unroll
        for (int kt = 0; kt < 4; kt++) {
            uint32_t a[4];
            ldsm4(a[0], a[1], a[2], a[3], sb + F_A + a_off + kt * 32);
            #pragma unroll
            for (int ntp = 0; ntp < 2; ntp++) {
                uint32_t b0, b1, b2, b3;
                ldsm4(b0, b1, b2, b3,
                      bB[pass] + b_off + (uint32_t)((cw + ntp * 16) * HSTR * 2) + kt * 32);
                mma16816h(acc[2 * ntp],     a, b0, b1);
                mma16816h(acc[2 * ntp + 1], a, b2, b3);
            }
        }
    }

    // ---- epilogue ----
    const int rA = rw + (lane >> 2);
    long long gA = base + rA, gB = gA + 8;
    bool vA = gA < NN, vB = gB < NN;
    #pragma unroll
    for (int nt = 0; nt < 4; nt++) {
        int cg = cw + nt * 8 + (lane & 3) * 2;
        if (Hout) {
            if (vA) *(__half2*)&Hout[gA * 64 + cg] =
                __floats2half2_rn(acc[nt][0], acc[nt][1]);
            if (vB) *(__half2*)&Hout[gB * 64 + cg] =
                __floats2half2_rn(acc[nt][2], acc[nt][3]);
        } else {
            float bx = bias_f[cg], by = bias_f[cg + 1];
            if (vA) {
                float2 o = make_float2(acc[nt][0] + bx, acc[nt][1] + by);
                *(float2*)&Fout[gA * 64 + cg] = o;
            }
            if (vB) {
                float2 o = make_float2(acc[nt][2] + bx, acc[nt][3] + by);
                *(float2*)&Fout[gB * 64 + cg] = o;
            }
        }
    }
}

// ---------------------------------------------------------------------------
extern "C" void kernel_launch(void* const* d_in, const int* in_sizes, int n_in,
                              void* d_out, int out_size) {
    const float* x    = (const float*)d_in[0];
    const void*  ei   = d_in[1];
    const float* Ws   = (const float*)d_in[2];
    const float* bs   = (const float*)d_in[3];
    const float* Wout = (const float*)d_in[4];
    const float* bout = (const float*)d_in[5];
    float* out = (float*)d_out;

    uint4 *hA, *hB;
    unsigned short *wh, *wl;
    cudaGetSymbolAddress((void**)&hA, g_hA);
    cudaGetSymbolAddress((void**)&hB, g_hB);
    cudaGetSymbolAddress((void**)&wh, g_wh);
    cudaGetSymbolAddress((void**)&wl, g_wl);

    cudaFuncSetAttribute(gemm_f32, cudaFuncAttributeMaxDynamicSharedMemorySize, G_TOT);
    cudaFuncSetAttribute(fused_gg, cudaFuncAttributeMaxDynamicSharedMemorySize, F_TOT);

    // Side stream + events, created once on the (uncaptured) correctness call.
    static cudaStream_t s2 = nullptr;
    static cudaEvent_t  ev_fork = nullptr, ev_g1 = nullptr;
    if (!s2) {
        cudaStreamCreateWithFlags(&s2, cudaStreamNonBlocking);
        cudaEventCreateWithFlags(&ev_fork, cudaEventDisableTiming);
        cudaEventCreateWithFlags(&ev_g1, cudaEventDisableTiming);
    }

    const int GB_E  = (NE + 255) / 256;
    const int GB_N  = (NN + 255) / 256;
    const int GB_MM = (NN + 127) / 128;
    const int GB_F  = (NN + 63) / 64;

    // Fork: GEMM-1 + weight-plane conversion (input-only deps) run on s2.
    cudaEventRecord(ev_fork, 0);
    cudaStreamWaitEvent(s2, ev_fork, 0);
    gemm_f32<<<GB_MM, 256, G_TOT, s2>>>(x, Ws, (__half*)hA);
    wconv<<<48, 256, 0, s2>>>(Ws, Wout);
    cudaEventRecord(ev_g1, s2);

    // CSR build on the main stream.
    degi_count<<<GB_E, 256>>>(ei);
    scan1<<<NSCB, SCAN_T>>>();
    scan23<<<GB_N, 256>>>();
    csr_fill<<<GB_E, 256>>>(ei);

    // Join, then 3 fused gather+gemm stages (ping-pong h buffers).
    cudaStreamWaitEvent(0, ev_g1, 0);
    fused_gg<<<GB_F, 256, F_TOT>>>(hA, bs,         wh,        wl,        (__half*)hB, nullptr, nullptr);
    fused_gg<<<GB_F, 256, F_TOT>>>(hB, bs + D,     wh + 4096, wl + 4096, (__half*)hA, nullptr, nullptr);
    fused_gg<<<GB_F, 256, F_TOT>>>(hA, bs + 2 * D, wh + 8192, wl + 8192, nullptr, out, bout);
}